// round 3
// baseline (speedup 1.0000x reference)
#include <cuda_runtime.h>
#include <cuda_bf16.h>
#include <math.h>

#define B_ 16
#define T_ 256
#define H_ 128
#define E_ 128
#define V_ 50000
#define G_ 512   /* 4*H */

// ---------------- scratch (no allocation allowed) ----------------
__device__ float g_xproj[(size_t)T_ * B_ * G_];   // 8 MB, reused by both layers
__device__ float g_y0[(size_t)T_ * B_ * H_];      // 2 MB, layout [T,B,H]
__device__ float g_y1[(size_t)B_ * T_ * H_];      // 2 MB, layout [B,T,H]

// ---------------- packed fp32x2 helpers (Blackwell FFMA2 path) ----------------
static __device__ __forceinline__ unsigned long long pk2(float x, float y) {
    unsigned long long r;
    asm("mov.b64 %0, {%1, %2};" : "=l"(r) : "f"(x), "f"(y));
    return r;
}
static __device__ __forceinline__ float2 upk2(unsigned long long v) {
    float2 r;
    asm("mov.b64 {%0, %1}, %2;" : "=f"(r.x), "=f"(r.y) : "l"(v));
    return r;
}
static __device__ __forceinline__ unsigned long long ffma2(
    unsigned long long a, unsigned long long b, unsigned long long c) {
    unsigned long long d;
    asm("fma.rn.f32x2 %0, %1, %2, %3;" : "=l"(d) : "l"(a), "l"(b), "l"(c));
    return d;
}

static __device__ __forceinline__ float sigf(float x) {
    return 1.0f / (1.0f + expf(-x));
}

// =====================================================================
// proj GEMM: out[r][g] = dot(A(r,:), Wih[g,:]) + bih[g] + bhh[g]
// rows r = t*B + b (4096 rows), N = 512, K = 128.
// If xidx != null, A row = emb[x[b][t]] (fused embedding gather).
// Tile 64x64, 256 threads, full-K in smem.
// =====================================================================
#define PROJ_SMEM (64 * 132 * 4 + 128 * 65 * 4)

__global__ __launch_bounds__(256) void proj_kernel(
    const float* __restrict__ Asrc, const int* __restrict__ xidx,
    const float* __restrict__ Wih, const float* __restrict__ bih,
    const float* __restrict__ bhh, float* __restrict__ out)
{
    extern __shared__ float sm[];
    float (*As)[132] = reinterpret_cast<float(*)[132]>(sm);          // 64 x 128 (+pad)
    float (*Ws)[65]  = reinterpret_cast<float(*)[65]>(sm + 64 * 132); // Ws[k][n]

    const int m0 = blockIdx.y * 64;
    const int n0 = blockIdx.x * 64;
    const int tid = threadIdx.x;

    // Load A tile (gathered for layer 0)
    for (int i = tid; i < 64 * 32; i += 256) {
        int r = i >> 5, c4 = (i & 31) * 4;
        const float* arow;
        if (xidx) {
            int gr = m0 + r;                 // gr = t*16 + b
            int b = gr & 15, t = gr >> 4;
            arow = Asrc + (size_t)xidx[b * T_ + t] * E_;
        } else {
            arow = Asrc + (size_t)(m0 + r) * H_;
        }
        float4 v = *reinterpret_cast<const float4*>(arow + c4);
        *reinterpret_cast<float4*>(&As[r][c4]) = v;
    }
    // Load W tile transposed: Ws[k][n] = Wih[n0+n][k]
    for (int i = tid; i < 64 * 32; i += 256) {
        int n = i >> 5, c4 = (i & 31) * 4;
        float4 v = *reinterpret_cast<const float4*>(Wih + (size_t)(n0 + n) * 128 + c4);
        Ws[c4 + 0][n] = v.x; Ws[c4 + 1][n] = v.y;
        Ws[c4 + 2][n] = v.z; Ws[c4 + 3][n] = v.w;
    }
    __syncthreads();

    const int tx = tid & 15, ty = tid >> 4;
    float acc[4][4] = {};
    #pragma unroll 8
    for (int k = 0; k < 128; k++) {
        float a[4], w[4];
        #pragma unroll
        for (int i = 0; i < 4; i++) a[i] = As[ty * 4 + i][k];
        #pragma unroll
        for (int j = 0; j < 4; j++) w[j] = Ws[k][tx * 4 + j];
        #pragma unroll
        for (int i = 0; i < 4; i++)
            #pragma unroll
            for (int j = 0; j < 4; j++)
                acc[i][j] = fmaf(a[i], w[j], acc[i][j]);
    }

    #pragma unroll
    for (int j = 0; j < 4; j++) {
        int n = n0 + tx * 4 + j;
        float bv = bih[n] + bhh[n];
        #pragma unroll
        for (int i = 0; i < 4; i++) {
            out[(size_t)(m0 + ty * 4 + i) * G_ + n] = acc[i][j] + bv;
        }
    }
}

// =====================================================================
// LSTM recurrence: one block per batch element (16 blocks), 512 threads
// (one gate each). h state in smem (broadcast reads), c in registers of
// threads 0..127. Gate dot products via packed fp32x2 FMA.
// layer==0: y layout [T,B,H]; layer==1: y layout [B,T,H].
// =====================================================================
__global__ __launch_bounds__(512, 1) void lstm_kernel(
    const float* __restrict__ xproj, const float* __restrict__ Whh,
    float* __restrict__ y, int layer,
    float* __restrict__ h_out, float* __restrict__ c_out)
{
    __shared__ float hs[H_];
    __shared__ float gs[G_];
    const int b = blockIdx.x;
    const int g = threadIdx.x;

    float c = 0.0f;
    if (g < H_) hs[g] = 0.0f;
    __syncthreads();

    const float4* w4 = reinterpret_cast<const float4*>(Whh + (size_t)g * H_);

    for (int t = 0; t < T_; t++) {
        unsigned long long acc = 0ull;  // packed {0.f, 0.f}
        const float4* h4 = reinterpret_cast<const float4*>(hs);
        #pragma unroll
        for (int k = 0; k < H_ / 4; k++) {
            float4 wv = w4[k];
            float4 hv = h4[k];
            acc = ffma2(pk2(wv.x, wv.y), pk2(hv.x, hv.y), acc);
            acc = ffma2(pk2(wv.z, wv.w), pk2(hv.z, hv.w), acc);
        }
        float2 p = upk2(acc);
        gs[g] = p.x + p.y + xproj[((size_t)t * B_ + b) * G_ + g];
        __syncthreads();

        if (g < H_) {
            float iv = sigf(gs[g]);
            float fv = sigf(gs[H_ + g]);
            float gv = tanhf(gs[2 * H_ + g]);
            float ov = sigf(gs[3 * H_ + g]);
            c = fv * c + iv * gv;
            float h = ov * tanhf(c);
            hs[g] = h;
            size_t row = (layer == 0) ? ((size_t)t * B_ + b) : ((size_t)b * T_ + t);
            y[row * H_ + g] = h;
        }
        __syncthreads();
    }

    if (g < H_) {
        h_out[b * H_ + g] = hs[g];
        c_out[b * H_ + g] = c;
    }
}

// =====================================================================
// FC GEMM: logits[r][v] = dot(y1[r,:], fc_w[v,:]) + fc_b[v]
// M=4096, N=50000, K=128. Tile 128x128, 256 threads, full K in smem.
// Packed fp32x2 over k-pairs: one FFMA2 = 2 fp32 FMAs (bit-exact fp32).
// B staged k2-major so per-k2 b-loads are 16 consecutive float2
// (conflict-free); thread columns are j*16+tx (coalesced stores).
// =====================================================================
#define FC_SMEM (128 * 132 * 4 + 64 * 128 * 8)

__global__ __launch_bounds__(256, 1) void fc_kernel(
    const float* __restrict__ A, const float* __restrict__ W,
    const float* __restrict__ bias, float* __restrict__ out)
{
    extern __shared__ float sm[];
    float (*As)[132] = reinterpret_cast<float(*)[132]>(sm);                 // 128 x 128 (+pad)
    unsigned long long* Bs = reinterpret_cast<unsigned long long*>(sm + 128 * 132); // [64 k2][128 n]

    const int n0 = blockIdx.x * 128;
    const int m0 = blockIdx.y * 128;
    const int tid = threadIdx.x;

    for (int i = tid; i < 128 * 32; i += 256) {
        int r = i >> 5, c4 = (i & 31) * 4;
        float4 v = *reinterpret_cast<const float4*>(A + (size_t)(m0 + r) * H_ + c4);
        *reinterpret_cast<float4*>(&As[r][c4]) = v;
    }
    for (int i = tid; i < 128 * 32; i += 256) {
        int n = i >> 5, c4 = i & 31;
        int vrow = n0 + n;
        float4 v = (vrow < V_)
            ? *reinterpret_cast<const float4*>(W + (size_t)vrow * H_ + c4 * 4)
            : make_float4(0.f, 0.f, 0.f, 0.f);
        Bs[(size_t)(2 * c4) * 128 + n]     = pk2(v.x, v.y);
        Bs[(size_t)(2 * c4 + 1) * 128 + n] = pk2(v.z, v.w);
    }
    __syncthreads();

    const int tx = tid & 15, ty = tid >> 4;
    unsigned long long acc[8][8];
    #pragma unroll
    for (int i = 0; i < 8; i++)
        #pragma unroll
        for (int j = 0; j < 8; j++) acc[i][j] = 0ull;

    #pragma unroll 8
    for (int k2 = 0; k2 < 64; k2++) {
        unsigned long long a[8], bb[8];
        #pragma unroll
        for (int i = 0; i < 8; i++) {
            float2 av = *reinterpret_cast<const float2*>(&As[ty * 8 + i][2 * k2]);
            a[i] = pk2(av.x, av.y);
        }
        #pragma unroll
        for (int j = 0; j < 8; j++) bb[j] = Bs[(size_t)k2 * 128 + j * 16 + tx];
        #pragma unroll
        for (int i = 0; i < 8; i++)
            #pragma unroll
            for (int j = 0; j < 8; j++)
                acc[i][j] = ffma2(a[i], bb[j], acc[i][j]);
    }

    #pragma unroll
    for (int j = 0; j < 8; j++) {
        int n = n0 + j * 16 + tx;
        if (n < V_) {
            float bv = bias[n];
            #pragma unroll
            for (int i = 0; i < 8; i++) {
                float2 p = upk2(acc[i][j]);
                out[(size_t)(m0 + ty * 8 + i) * V_ + n] = p.x + p.y + bv;
            }
        }
    }
}

// =====================================================================
// launch
// =====================================================================
extern "C" void kernel_launch(void* const* d_in, const int* in_sizes, int n_in,
                              void* d_out, int out_size)
{
    const int*   x    = (const int*)  d_in[0];
    const float* emb  = (const float*)d_in[1];
    const float* Wih0 = (const float*)d_in[2];
    const float* Whh0 = (const float*)d_in[3];
    const float* bih0 = (const float*)d_in[4];
    const float* bhh0 = (const float*)d_in[5];
    const float* Wih1 = (const float*)d_in[6];
    const float* Whh1 = (const float*)d_in[7];
    const float* bih1 = (const float*)d_in[8];
    const float* bhh1 = (const float*)d_in[9];
    const float* fcw  = (const float*)d_in[10];
    const float* fcb  = (const float*)d_in[11];
    float* out = (float*)d_out;

    float *xproj, *y0, *y1;
    cudaGetSymbolAddress((void**)&xproj, g_xproj);
    cudaGetSymbolAddress((void**)&y0, g_y0);
    cudaGetSymbolAddress((void**)&y1, g_y1);

    cudaFuncSetAttribute(proj_kernel, cudaFuncAttributeMaxDynamicSharedMemorySize, PROJ_SMEM);
    cudaFuncSetAttribute(fc_kernel,  cudaFuncAttributeMaxDynamicSharedMemorySize, FC_SMEM);

    // output layout: logits [B,T,V] || h [L,B,H] || c [L,B,H]
    const size_t NL = (size_t)B_ * T_ * V_;
    float* h_base = out + NL;
    float* c_base = out + NL + 2 * B_ * H_;

    // layer 0
    proj_kernel<<<dim3(8, 64), 256, PROJ_SMEM>>>(emb, x, Wih0, bih0, bhh0, xproj);
    lstm_kernel<<<16, 512>>>(xproj, Whh0, y0, 0, h_base, c_base);
    // layer 1
    proj_kernel<<<dim3(8, 64), 256, PROJ_SMEM>>>(y0, nullptr, Wih1, bih1, bhh1, xproj);
    lstm_kernel<<<16, 512>>>(xproj, Whh1, y1, 1, h_base + B_ * H_, c_base + B_ * H_);
    // output projection
    fc_kernel<<<dim3((V_ + 127) / 128, 32), 256, FC_SMEM>>>(y1, fcw, fcb, out);
}